// round 15
// baseline (speedup 1.0000x reference)
#include <cuda_runtime.h>
#include <cuda_fp16.h>
#include <cstdint>
#include <math.h>

// Problem constants
#define BB   2
#define SS   2048
#define DIN  1024
#define DD   1024
#define HH   16
#define HDIM 64
#define M_ROWS (BB * SS)      // 4096
#define QKV_N  (3 * DD)       // 3072

// Scratch
__device__ __half g_qkvh [M_ROWS * QKV_N];
__device__ __half g_xc   [M_ROWS * DIN];
__device__ __half g_valsp[M_ROWS * DD];
__device__ __half g_wqc  [QKV_N * DIN];
__device__ __half g_woc  [DD * DD];
__device__ __half g_kvp  [BB * HH * 32 * 8192];

// ---------------------------------------------------------------------------
// Helpers
// ---------------------------------------------------------------------------
__device__ __forceinline__ uint32_t smem_u32(const void* p) {
    uint32_t a;
    asm("{ .reg .u64 t; cvta.to.shared.u64 t, %1; cvt.u32.u64 %0, t; }"
        : "=r"(a) : "l"(p));
    return a;
}

__device__ __forceinline__ uint32_t f2h2(float a, float b) {
    __half2 h = __floats2half2_rn(a, b);
    return *(uint32_t*)&h;
}

__device__ __forceinline__ float ex2(float x) {
    float r;
    asm("ex2.approx.f32 %0, %1;" : "=f"(r) : "f"(x));
    return r;
}

__device__ __forceinline__ void mma_f16(float* d, const uint32_t* a, const uint32_t* b) {
    asm("mma.sync.aligned.m16n8k16.row.col.f32.f16.f16.f32 "
        "{%0,%1,%2,%3}, {%4,%5,%6,%7}, {%8,%9}, {%0,%1,%2,%3};"
        : "+f"(d[0]), "+f"(d[1]), "+f"(d[2]), "+f"(d[3])
        : "r"(a[0]), "r"(a[1]), "r"(a[2]), "r"(a[3]),
          "r"(b[0]), "r"(b[1]));
}

#define MBAR_INIT(mbar, cnt) \
    asm volatile("mbarrier.init.shared.b64 [%0], %1;" \
        :: "r"((uint32_t)(mbar)), "r"((uint32_t)(cnt)) : "memory")

#define MBAR_EXPECT_TX(mbar, bytes) \
    asm volatile("mbarrier.arrive.expect_tx.shared.b64 _, [%0], %1;" \
        :: "r"((uint32_t)(mbar)), "r"((uint32_t)(bytes)) : "memory")

#define MBAR_WAIT(mbar, parity) do { \
    asm volatile( \
        "{\n\t.reg .pred P1;\n\t" \
        "WL_%=:\n\t" \
        "mbarrier.try_wait.parity.shared.b64 P1, [%0], %1;\n\t" \
        "@P1 bra.uni WD_%=;\n\t" \
        "bra.uni WL_%=;\n\t" \
        "WD_%=:\n\t}" \
        :: "r"((uint32_t)(mbar)), "r"((uint32_t)(parity)) : "memory"); \
} while (0)

#define BULK_CP(dst, src, bytes, mbar) \
    asm volatile("cp.async.bulk.shared::cluster.global.mbarrier::complete_tx::bytes " \
        "[%0], [%1], %2, [%3];" \
        :: "r"((uint32_t)(dst)), "l"(src), "r"((uint32_t)(bytes)), \
           "r"((uint32_t)(mbar)) : "memory")

#define FENCE_PROXY() asm volatile("fence.proxy.async.shared::cta;" ::: "memory")

// ---------------------------------------------------------------------------
// Pack kernels (unchanged).
// ---------------------------------------------------------------------------
#define PSTR 68

__global__ __launch_bounds__(256) void pack_a_h(
    const float* __restrict__ src, __half* __restrict__ dst, int K)
{
    __shared__ float sm[128 * PSTR];
    const int tid = threadIdx.x;
    const int KT = K / 64;
    const int kt = blockIdx.x % KT;
    const int mt = blockIdx.x / KT;
    const float* g = src + (size_t)(mt * 128) * K + kt * 64;
#pragma unroll
    for (int it = 0; it < 8; it++) {
        int idx = it * 256 + tid;
        int r = idx >> 4;
        int c4 = (idx & 15) * 4;
        *(float4*)&sm[r * PSTR + c4] = *(const float4*)(g + (size_t)r * K + c4);
    }
    __syncthreads();
    uint4* o = (uint4*)(dst + (size_t)blockIdx.x * 8192);
#pragma unroll
    for (int it = 0; it < 4; it++) {
        int q = it * 256 + tid;
        int grp = q >> 7;
        int ks = (q >> 5) & 3;
        int lane = q & 31;
        int gid = lane >> 2, tig = lane & 3;
        int r0 = grp * 16 + gid;
        int kb = ks * 16 + 2 * tig;
        uint4 w;
        w.x = f2h2(sm[r0 * PSTR + kb],           sm[r0 * PSTR + kb + 1]);
        w.y = f2h2(sm[(r0 + 8) * PSTR + kb],     sm[(r0 + 8) * PSTR + kb + 1]);
        w.z = f2h2(sm[r0 * PSTR + kb + 8],       sm[r0 * PSTR + kb + 9]);
        w.w = f2h2(sm[(r0 + 8) * PSTR + kb + 8], sm[(r0 + 8) * PSTR + kb + 9]);
        o[q] = w;
    }
}

__global__ __launch_bounds__(256) void pack_b_h(
    const float* __restrict__ src, __half* __restrict__ dst, int K)
{
    __shared__ float sm[128 * PSTR];
    const int tid = threadIdx.x;
    const int KT = K / 64;
    const int kt = blockIdx.x % KT;
    const int nt = blockIdx.x / KT;
    const float* g = src + (size_t)(nt * 128) * K + kt * 64;
#pragma unroll
    for (int it = 0; it < 8; it++) {
        int idx = it * 256 + tid;
        int r = idx >> 4;
        int c4 = (idx & 15) * 4;
        *(float4*)&sm[r * PSTR + c4] = *(const float4*)(g + (size_t)r * K + c4);
    }
    __syncthreads();
    uint2* o = (uint2*)(dst + (size_t)blockIdx.x * 8192);
#pragma unroll
    for (int it = 0; it < 8; it++) {
        int q = it * 256 + tid;
        int ngrp = q >> 7;
        int ks = (q >> 5) & 3;
        int lane = q & 31;
        int gid = lane >> 2, tig = lane & 3;
        int n = ngrp * 8 + gid;
        int kb = ks * 16 + 2 * tig;
        uint2 w;
        w.x = f2h2(sm[n * PSTR + kb],     sm[n * PSTR + kb + 1]);
        w.y = f2h2(sm[n * PSTR + kb + 8], sm[n * PSTR + kb + 9]);
        o[q] = w;
    }
}

#define HSTR 136
__global__ __launch_bounds__(256) void pack_kv_h(
    const __half* __restrict__ qkvh, __half* __restrict__ kvp)
{
    __shared__ __half kv[64 * HSTR];
    const int tid = threadIdx.x;
    const int kt = blockIdx.x;
    const int h  = blockIdx.y;
    const int b  = blockIdx.z;

    const __half* src = qkvh + (size_t)(b * SS + kt * 64) * QKV_N + h * 192 + 64;
#pragma unroll
    for (int it = 0; it < 4; it++) {
        int idx = it * 256 + tid;
        int row = idx >> 4;
        int c8  = (idx & 15) * 8;
        *(uint4*)&kv[row * HSTR + c8] = *(const uint4*)(src + (size_t)row * QKV_N + c8);
    }
    __syncthreads();

    uint2* ko = (uint2*)(kvp + (size_t)((b * HH + h) * 32 + kt) * 8192);
    uint2* vo = ko + 1024;
#pragma unroll
    for (int it = 0; it < 4; it++) {
        int q = it * 256 + tid;
        int lane = q & 31;
        int gid = lane >> 2, tig = lane & 3;
        {
            int nt = q >> 7;
            int ks = (q >> 5) & 3;
            int key = nt * 8 + gid;
            int kb = ks * 16 + 2 * tig;
            uint2 w;
            w.x = *(const uint32_t*)&kv[key * HSTR + kb];
            w.y = *(const uint32_t*)&kv[key * HSTR + kb + 8];
            ko[q] = w;
        }
        {
            int j = q >> 8;
            int nt2 = (q >> 5) & 7;
            int d = 64 + nt2 * 8 + gid;
            int kr = j * 16 + 2 * tig;
            __half2 a = __halves2half2(kv[kr * HSTR + d],       kv[(kr + 1) * HSTR + d]);
            __half2 c = __halves2half2(kv[(kr + 8) * HSTR + d], kv[(kr + 9) * HSTR + d]);
            uint2 w;
            w.x = *(uint32_t*)&a;
            w.y = *(uint32_t*)&c;
            vo[q] = w;
        }
    }
}

// ---------------------------------------------------------------------------
// fp16 GEMM, warp tile 64x64, CTA 128x128, 4 warps.
// ROUND 15: 3-stage bulk pipeline (2 loads always in flight -> mbar waits
// pre-satisfied), 2 CTAs/SM, wide inner loop (afr[4] preloaded).
// SMEM: [A0 16K][A1][A2][B0][B1][B2][mbar x3]
// ---------------------------------------------------------------------------
#define GSTG 3
#define GEMM_SMEM_BYTES (GSTG * 32768 + 24)   // 98328

__global__ __launch_bounds__(128, 2) void gemm_h(
    const __half* __restrict__ A, const __half* __restrict__ Bw,
    const float* __restrict__ bias, float* __restrict__ C,
    __half* __restrict__ Ch,
    int M, int N, int K, int out_half)
{
    extern __shared__ char smc[];
    const uint32_t sb = smem_u32(smc);
    const uint32_t mb = sb + GSTG * 32768;
    const int tid  = threadIdx.x;
    const int wid  = tid >> 5;
    const int lane = tid & 31;
    const int gid  = lane >> 2;
    const int tig  = lane & 3;
    const int wm8  = (wid >> 1) * 4;
    const int wn16 = (wid & 1) * 8;
    const int m0 = blockIdx.y * 128;
    const int n0 = blockIdx.x * 128;
    const int KT = K / 64;

    if (tid == 0) {
        MBAR_INIT(mb, 1);
        MBAR_INIT(mb + 8, 1);
        MBAR_INIT(mb + 16, 1);
        FENCE_PROXY();
    }
    __syncthreads();

    float acc[4][8][4];
#pragma unroll
    for (int i = 0; i < 4; i++)
#pragma unroll
        for (int j = 0; j < 8; j++)
#pragma unroll
            for (int r = 0; r < 4; r++) acc[i][j][r] = 0.f;

    const __half* abase = A + ((size_t)blockIdx.y * KT) * 8192;
    const __half* bbase = Bw + ((size_t)blockIdx.x * KT) * 8192;

    auto load_stage = [&](int chunk, int stage) {
        MBAR_EXPECT_TX(mb + stage * 8, 32768);
        BULK_CP(sb + stage * 16384,                 abase + (size_t)chunk * 8192, 16384, mb + stage * 8);
        BULK_CP(sb + GSTG * 16384 + stage * 16384,  bbase + (size_t)chunk * 8192, 16384, mb + stage * 8);
    };

    if (tid == 0) {
        load_stage(0, 0);
        load_stage(1, 1);
    }

    int cstage = 0;   // stage of chunk j
    int phase  = 0;   // parity for cstage
    int pcount = 0;
    for (int j = 0; j < KT; j++) {
        MBAR_WAIT(mb + cstage * 8, phase);
        __syncthreads();   // all warps done with compute(j-1) -> stage (j+2)%3 free
        if (tid == 0 && j + 2 < KT) {
            int ls = cstage == 0 ? 2 : cstage - 1;   // (j+2)%3 = (j-1)%3
            load_stage(j + 2, ls);
        }

        const uint4* at4 = (const uint4*)(smc + cstage * 16384);
        const uint2* bt2 = (const uint2*)(smc + GSTG * 16384 + cstage * 16384);

#pragma unroll
        for (int ks = 0; ks < 4; ks++) {
            uint4 afr[4];
#pragma unroll
            for (int mt = 0; mt < 4; mt++)
                afr[mt] = at4[(((wm8 + mt) * 4 + ks) << 5) + lane];
            uint2 bfr[8];
#pragma unroll
            for (int nt = 0; nt < 8; nt++)
                bfr[nt] = bt2[(((wn16 + nt) * 4 + ks) << 5) + lane];
#pragma unroll
            for (int mt = 0; mt < 4; mt++)
#pragma unroll
                for (int nt = 0; nt < 8; nt++)
                    mma_f16(acc[mt][nt],
                            (const uint32_t*)&afr[mt],
                            (const uint32_t*)&bfr[nt]);
        }
        // advance ring
        cstage = (cstage == GSTG - 1) ? 0 : cstage + 1;
        if (++pcount == GSTG) { pcount = 0; phase ^= 1; }
    }

#pragma unroll
    for (int mt = 0; mt < 4; mt++) {
        const int row = m0 + (wid >> 1) * 64 + mt * 16 + gid;
#pragma unroll
        for (int nt = 0; nt < 8; nt++) {
            const int col = n0 + (wid & 1) * 64 + nt * 8 + tig * 2;
            float2 bv = *(const float2*)(bias + col);
            float o0x = acc[mt][nt][0] + bv.x;
            float o0y = acc[mt][nt][1] + bv.y;
            float o1x = acc[mt][nt][2] + bv.x;
            float o1y = acc[mt][nt][3] + bv.y;
            if (out_half) {
                *(uint32_t*)(Ch + (size_t)row * N + col) = f2h2(o0x, o0y);
                *(uint32_t*)(Ch + (size_t)(row + 8) * N + col) = f2h2(o1x, o1y);
            } else {
                *(float2*)(C + (size_t)row * N + col) = make_float2(o0x, o0y);
                *(float2*)(C + (size_t)(row + 8) * N + col) = make_float2(o1x, o1y);
            }
        }
    }
}

// ---------------------------------------------------------------------------
// fp16 flash attention (unchanged from round 14).
// ---------------------------------------------------------------------------
#define ATT_SMEM_BYTES (32768 + 16)

__global__ __launch_bounds__(128, 2) void attn_h(
    const __half* __restrict__ qkvh, const __half* __restrict__ kvp,
    __half* __restrict__ valsp)
{
    extern __shared__ char smc[];
    const uint32_t sb = smem_u32(smc);
    const uint32_t mb = sb + 32768;

    const int tid  = threadIdx.x;
    const int wid  = tid >> 5;
    const int lane = tid & 31;
    const int gid  = lane >> 2;
    const int tig  = lane & 3;
    const int b  = blockIdx.z;
    const int h  = blockIdx.y;
    const int q0 = blockIdx.x * 128;

    const float qs = 0.125f * 1.4426950408889634f;

    if (tid == 0) {
        MBAR_INIT(mb, 1);
        MBAR_INIT(mb + 8, 1);
        FENCE_PROXY();
    }
    __syncthreads();

    uint32_t qf[2][4][4];
#pragma unroll
    for (int m = 0; m < 2; m++) {
        const __half* qlo = qkvh + (size_t)(b * SS + q0 + wid * 32 + m * 16 + gid) * QKV_N + h * 192;
        const __half* qhi = qlo + 8 * QKV_N;
#pragma unroll
        for (int ks = 0; ks < 4; ks++) {
            const int kb = ks * 16 + 2 * tig;
            qf[m][ks][0] = f2h2(__half2float(qlo[kb]) * qs,     __half2float(qlo[kb + 1]) * qs);
            qf[m][ks][1] = f2h2(__half2float(qhi[kb]) * qs,     __half2float(qhi[kb + 1]) * qs);
            qf[m][ks][2] = f2h2(__half2float(qlo[kb + 8]) * qs, __half2float(qlo[kb + 9]) * qs);
            qf[m][ks][3] = f2h2(__half2float(qhi[kb + 8]) * qs, __half2float(qhi[kb + 9]) * qs);
        }
    }

    const __half* kvbase = kvp + (size_t)(b * HH + h) * 32 * 8192;
    auto load_tile = [&](int kt) {
        const int stage = kt & 1;
        MBAR_EXPECT_TX(mb + stage * 8, 16384);
        BULK_CP(sb + stage * 16384, kvbase + (size_t)kt * 8192, 16384, mb + stage * 8);
    };

    float mx[2][2], lx[2][2];
#pragma unroll
    for (int m = 0; m < 2; m++) {
        mx[m][0] = mx[m][1] = -1e30f;
        lx[m][0] = lx[m][1] = 0.f;
    }
    float oacc[2][8][4];
#pragma unroll
    for (int m = 0; m < 2; m++)
#pragma unroll
        for (int nt = 0; nt < 8; nt++)
#pragma unroll
            for (int r = 0; r < 4; r++) oacc[m][nt][r] = 0.f;

    if (tid == 0) load_tile(0);

    const int NT = SS / 64;
    for (int kt = 0; kt < NT; kt++) {
        MBAR_WAIT(mb + (kt & 1) * 8, (kt >> 1) & 1);
        __syncthreads();
        if (tid == 0 && kt + 1 < NT) load_tile(kt + 1);

        const uint2* kp2 = (const uint2*)(smc + (kt & 1) * 16384);
        const uint2* vp2 = kp2 + 1024;

        float sacc[2][8][4];
#pragma unroll
        for (int m = 0; m < 2; m++)
#pragma unroll
            for (int nt = 0; nt < 8; nt++)
#pragma unroll
                for (int r = 0; r < 4; r++) sacc[m][nt][r] = 0.f;

#pragma unroll
        for (int ks = 0; ks < 4; ks++) {
            uint2 kfr[8];
#pragma unroll
            for (int nt = 0; nt < 8; nt++)
                kfr[nt] = kp2[((nt * 4 + ks) << 5) + lane];
#pragma unroll
            for (int m = 0; m < 2; m++)
#pragma unroll
                for (int nt = 0; nt < 8; nt++)
                    mma_f16(sacc[m][nt], qf[m][ks], (const uint32_t*)&kfr[nt]);
        }

        uint32_t pf[2][4][4];
#pragma unroll
        for (int m = 0; m < 2; m++) {
            float tmax0 = -1e30f, tmax1 = -1e30f;
#pragma unroll
            for (int nt = 0; nt < 8; nt++) {
                tmax0 = fmaxf(tmax0, fmaxf(sacc[m][nt][0], sacc[m][nt][1]));
                tmax1 = fmaxf(tmax1, fmaxf(sacc[m][nt][2], sacc[m][nt][3]));
            }
            tmax0 = fmaxf(tmax0, __shfl_xor_sync(0xffffffffu, tmax0, 1));
            tmax0 = fmaxf(tmax0, __shfl_xor_sync(0xffffffffu, tmax0, 2));
            tmax1 = fmaxf(tmax1, __shfl_xor_sync(0xffffffffu, tmax1, 1));
            tmax1 = fmaxf(tmax1, __shfl_xor_sync(0xffffffffu, tmax1, 2));

            const float mn0 = fmaxf(mx[m][0], tmax0);
            const float mn1 = fmaxf(mx[m][1], tmax1);
            const float corr0 = ex2(mx[m][0] - mn0);
            const float corr1 = ex2(mx[m][1] - mn1);
            mx[m][0] = mn0;
            mx[m][1] = mn1;

            float sum0 = 0.f, sum1 = 0.f;
#pragma unroll
            for (int nt = 0; nt < 8; nt++) {
                float p0 = ex2(sacc[m][nt][0] - mn0);
                float p1 = ex2(sacc[m][nt][1] - mn0);
                float p2 = ex2(sacc[m][nt][2] - mn1);
                float p3 = ex2(sacc[m][nt][3] - mn1);
                sum0 += p0 + p1;
                sum1 += p2 + p3;
                const int j = nt >> 1;
                if ((nt & 1) == 0) {
                    pf[m][j][0] = f2h2(p0, p1);
                    pf[m][j][1] = f2h2(p2, p3);
                } else {
                    pf[m][j][2] = f2h2(p0, p1);
                    pf[m][j][3] = f2h2(p2, p3);
                }
            }
#pragma unroll
            for (int nt = 0; nt < 8; nt++) {
                oacc[m][nt][0] *= corr0;
                oacc[m][nt][1] *= corr0;
                oacc[m][nt][2] *= corr1;
                oacc[m][nt][3] *= corr1;
            }
            lx[m][0] = lx[m][0] * corr0 + sum0;
            lx[m][1] = lx[m][1] * corr1 + sum1;
        }

#pragma unroll
        for (int j = 0; j < 4; j++) {
            uint2 vfr[8];
#pragma unroll
            for (int nt = 0; nt < 8; nt++)
                vfr[nt] = vp2[((j * 8 + nt) << 5) + lane];
#pragma unroll
            for (int m = 0; m < 2; m++)
#pragma unroll
                for (int nt = 0; nt < 8; nt++)
                    mma_f16(oacc[m][nt], pf[m][j], (const uint32_t*)&vfr[nt]);
        }
    }

    {
        const size_t mtile = (size_t)(b * SS + q0) >> 7;
        uint4* o = (uint4*)(valsp + (mtile * 16 + h) * 8192);
#pragma unroll
        for (int m = 0; m < 2; m++) {
            float l0 = lx[m][0], l1 = lx[m][1];
            l0 += __shfl_xor_sync(0xffffffffu, l0, 1);
            l0 += __shfl_xor_sync(0xffffffffu, l0, 2);
            l1 += __shfl_xor_sync(0xffffffffu, l1, 1);
            l1 += __shfl_xor_sync(0xffffffffu, l1, 2);
            const float inv0 = 1.f / l0;
            const float inv1 = 1.f / l1;
            const int grp = wid * 2 + m;
#pragma unroll
            for (int ks = 0; ks < 4; ks++) {
                uint4 w;
                w.x = f2h2(oacc[m][2 * ks][0] * inv0,     oacc[m][2 * ks][1] * inv0);
                w.y = f2h2(oacc[m][2 * ks][2] * inv1,     oacc[m][2 * ks][3] * inv1);
                w.z = f2h2(oacc[m][2 * ks + 1][0] * inv0, oacc[m][2 * ks + 1][1] * inv0);
                w.w = f2h2(oacc[m][2 * ks + 1][2] * inv1, oacc[m][2 * ks + 1][3] * inv1);
                o[((grp * 4 + ks) << 5) + lane] = w;
            }
        }
    }
}

// ---------------------------------------------------------------------------
// Launch
// ---------------------------------------------------------------------------
extern "C" void kernel_launch(void* const* d_in, const int* in_sizes, int n_in,
                              void* d_out, int out_size)
{
    const float* x      = (const float*)d_in[0];
    const float* w_qkv  = (const float*)d_in[1];
    const float* b_qkv  = (const float*)d_in[2];
    const float* w_o    = (const float*)d_in[3];
    const float* b_o    = (const float*)d_in[4];
    float* out = (float*)d_out;

    __half *qkvh, *xc, *valsp, *wqc, *woc, *kvp;
    cudaGetSymbolAddress((void**)&qkvh,  g_qkvh);
    cudaGetSymbolAddress((void**)&xc,    g_xc);
    cudaGetSymbolAddress((void**)&valsp, g_valsp);
    cudaGetSymbolAddress((void**)&wqc,   g_wqc);
    cudaGetSymbolAddress((void**)&woc,   g_woc);
    cudaGetSymbolAddress((void**)&kvp,   g_kvp);

    cudaFuncSetAttribute(gemm_h,
                         cudaFuncAttributeMaxDynamicSharedMemorySize,
                         GEMM_SMEM_BYTES);
    cudaFuncSetAttribute(attn_h,
                         cudaFuncAttributeMaxDynamicSharedMemorySize,
                         ATT_SMEM_BYTES);

    // 0) fragment-pack GEMM inputs into fp16
    pack_a_h<<<(M_ROWS / 128) * (DIN / 64), 256>>>(x, xc, DIN);
    pack_b_h<<<(QKV_N / 128) * (DIN / 64), 256>>>(w_qkv, wqc, DIN);
    pack_b_h<<<(DD / 128) * (DIN / 64), 256>>>(w_o, woc, DIN);

    // 1) QKV projection -> g_qkvh (fp16 row-major)
    {
        dim3 grid(QKV_N / 128, M_ROWS / 128);
        gemm_h<<<grid, 128, GEMM_SMEM_BYTES>>>(
            xc, wqc, b_qkv, nullptr, qkvh, M_ROWS, QKV_N, DIN, 1);
    }

    // 1b) fragment-pack K/V tiles
    {
        dim3 grid(SS / 64, HH, BB);
        pack_kv_h<<<grid, 256>>>(qkvh, kvp);
    }

    // 2) Attention -> g_valsp (fp16 A-frag-packed)
    {
        dim3 grid(SS / 128, HH, BB);
        attn_h<<<grid, 128, ATT_SMEM_BYTES>>>(qkvh, kvp, valsp);
    }

    // 3) O-projection -> out (fp32)
    {
        dim3 grid(DD / 128, M_ROWS / 128);
        gemm_h<<<grid, 128, GEMM_SMEM_BYTES>>>(
            valsp, woc, b_o, out, nullptr, M_ROWS, DD, DIN, 0);
    }
}

// round 16
// speedup vs baseline: 1.0120x; 1.0120x over previous
#include <cuda_runtime.h>
#include <cuda_fp16.h>
#include <cstdint>
#include <math.h>

// Problem constants
#define BB   2
#define SS   2048
#define DIN  1024
#define DD   1024
#define HH   16
#define HDIM 64
#define M_ROWS (BB * SS)      // 4096
#define QKV_N  (3 * DD)       // 3072

// Scratch
__device__ __half g_qkvh [M_ROWS * QKV_N];
__device__ __half g_xc   [M_ROWS * DIN];
__device__ __half g_valsp[M_ROWS * DD];
__device__ __half g_wqc  [QKV_N * DIN];
__device__ __half g_woc  [DD * DD];
__device__ __half g_kvp  [BB * HH * 32 * 8192];

// ---------------------------------------------------------------------------
// Helpers
// ---------------------------------------------------------------------------
__device__ __forceinline__ uint32_t smem_u32(const void* p) {
    uint32_t a;
    asm("{ .reg .u64 t; cvta.to.shared.u64 t, %1; cvt.u32.u64 %0, t; }"
        : "=r"(a) : "l"(p));
    return a;
}

__device__ __forceinline__ uint32_t f2h2(float a, float b) {
    __half2 h = __floats2half2_rn(a, b);
    return *(uint32_t*)&h;
}

__device__ __forceinline__ float ex2(float x) {
    float r;
    asm("ex2.approx.f32 %0, %1;" : "=f"(r) : "f"(x));
    return r;
}

__device__ __forceinline__ void mma_f16(float* d, const uint32_t* a, const uint32_t* b) {
    asm("mma.sync.aligned.m16n8k16.row.col.f32.f16.f16.f32 "
        "{%0,%1,%2,%3}, {%4,%5,%6,%7}, {%8,%9}, {%0,%1,%2,%3};"
        : "+f"(d[0]), "+f"(d[1]), "+f"(d[2]), "+f"(d[3])
        : "r"(a[0]), "r"(a[1]), "r"(a[2]), "r"(a[3]),
          "r"(b[0]), "r"(b[1]));
}

#define MBAR_INIT(mbar, cnt) \
    asm volatile("mbarrier.init.shared.b64 [%0], %1;" \
        :: "r"((uint32_t)(mbar)), "r"((uint32_t)(cnt)) : "memory")

#define MBAR_EXPECT_TX(mbar, bytes) \
    asm volatile("mbarrier.arrive.expect_tx.shared.b64 _, [%0], %1;" \
        :: "r"((uint32_t)(mbar)), "r"((uint32_t)(bytes)) : "memory")

#define MBAR_WAIT(mbar, parity) do { \
    asm volatile( \
        "{\n\t.reg .pred P1;\n\t" \
        "WL_%=:\n\t" \
        "mbarrier.try_wait.parity.shared.b64 P1, [%0], %1;\n\t" \
        "@P1 bra.uni WD_%=;\n\t" \
        "bra.uni WL_%=;\n\t" \
        "WD_%=:\n\t}" \
        :: "r"((uint32_t)(mbar)), "r"((uint32_t)(parity)) : "memory"); \
} while (0)

#define BULK_CP(dst, src, bytes, mbar) \
    asm volatile("cp.async.bulk.shared::cluster.global.mbarrier::complete_tx::bytes " \
        "[%0], [%1], %2, [%3];" \
        :: "r"((uint32_t)(dst)), "l"(src), "r"((uint32_t)(bytes)), \
           "r"((uint32_t)(mbar)) : "memory")

#define FENCE_PROXY() asm volatile("fence.proxy.async.shared::cta;" ::: "memory")

// ---------------------------------------------------------------------------
// Pack kernels (unchanged).
// ---------------------------------------------------------------------------
#define PSTR 68

__global__ __launch_bounds__(256) void pack_a_h(
    const float* __restrict__ src, __half* __restrict__ dst, int K)
{
    __shared__ float sm[128 * PSTR];
    const int tid = threadIdx.x;
    const int KT = K / 64;
    const int kt = blockIdx.x % KT;
    const int mt = blockIdx.x / KT;
    const float* g = src + (size_t)(mt * 128) * K + kt * 64;
#pragma unroll
    for (int it = 0; it < 8; it++) {
        int idx = it * 256 + tid;
        int r = idx >> 4;
        int c4 = (idx & 15) * 4;
        *(float4*)&sm[r * PSTR + c4] = *(const float4*)(g + (size_t)r * K + c4);
    }
    __syncthreads();
    uint4* o = (uint4*)(dst + (size_t)blockIdx.x * 8192);
#pragma unroll
    for (int it = 0; it < 4; it++) {
        int q = it * 256 + tid;
        int grp = q >> 7;
        int ks = (q >> 5) & 3;
        int lane = q & 31;
        int gid = lane >> 2, tig = lane & 3;
        int r0 = grp * 16 + gid;
        int kb = ks * 16 + 2 * tig;
        uint4 w;
        w.x = f2h2(sm[r0 * PSTR + kb],           sm[r0 * PSTR + kb + 1]);
        w.y = f2h2(sm[(r0 + 8) * PSTR + kb],     sm[(r0 + 8) * PSTR + kb + 1]);
        w.z = f2h2(sm[r0 * PSTR + kb + 8],       sm[r0 * PSTR + kb + 9]);
        w.w = f2h2(sm[(r0 + 8) * PSTR + kb + 8], sm[(r0 + 8) * PSTR + kb + 9]);
        o[q] = w;
    }
}

__global__ __launch_bounds__(256) void pack_b_h(
    const float* __restrict__ src, __half* __restrict__ dst, int K)
{
    __shared__ float sm[128 * PSTR];
    const int tid = threadIdx.x;
    const int KT = K / 64;
    const int kt = blockIdx.x % KT;
    const int nt = blockIdx.x / KT;
    const float* g = src + (size_t)(nt * 128) * K + kt * 64;
#pragma unroll
    for (int it = 0; it < 8; it++) {
        int idx = it * 256 + tid;
        int r = idx >> 4;
        int c4 = (idx & 15) * 4;
        *(float4*)&sm[r * PSTR + c4] = *(const float4*)(g + (size_t)r * K + c4);
    }
    __syncthreads();
    uint2* o = (uint2*)(dst + (size_t)blockIdx.x * 8192);
#pragma unroll
    for (int it = 0; it < 8; it++) {
        int q = it * 256 + tid;
        int ngrp = q >> 7;
        int ks = (q >> 5) & 3;
        int lane = q & 31;
        int gid = lane >> 2, tig = lane & 3;
        int n = ngrp * 8 + gid;
        int kb = ks * 16 + 2 * tig;
        uint2 w;
        w.x = f2h2(sm[n * PSTR + kb],     sm[n * PSTR + kb + 1]);
        w.y = f2h2(sm[n * PSTR + kb + 8], sm[n * PSTR + kb + 9]);
        o[q] = w;
    }
}

#define HSTR 136
__global__ __launch_bounds__(256) void pack_kv_h(
    const __half* __restrict__ qkvh, __half* __restrict__ kvp)
{
    __shared__ __half kv[64 * HSTR];
    const int tid = threadIdx.x;
    const int kt = blockIdx.x;
    const int h  = blockIdx.y;
    const int b  = blockIdx.z;

    const __half* src = qkvh + (size_t)(b * SS + kt * 64) * QKV_N + h * 192 + 64;
#pragma unroll
    for (int it = 0; it < 4; it++) {
        int idx = it * 256 + tid;
        int row = idx >> 4;
        int c8  = (idx & 15) * 8;
        *(uint4*)&kv[row * HSTR + c8] = *(const uint4*)(src + (size_t)row * QKV_N + c8);
    }
    __syncthreads();

    uint2* ko = (uint2*)(kvp + (size_t)((b * HH + h) * 32 + kt) * 8192);
    uint2* vo = ko + 1024;
#pragma unroll
    for (int it = 0; it < 4; it++) {
        int q = it * 256 + tid;
        int lane = q & 31;
        int gid = lane >> 2, tig = lane & 3;
        {
            int nt = q >> 7;
            int ks = (q >> 5) & 3;
            int key = nt * 8 + gid;
            int kb = ks * 16 + 2 * tig;
            uint2 w;
            w.x = *(const uint32_t*)&kv[key * HSTR + kb];
            w.y = *(const uint32_t*)&kv[key * HSTR + kb + 8];
            ko[q] = w;
        }
        {
            int j = q >> 8;
            int nt2 = (q >> 5) & 7;
            int d = 64 + nt2 * 8 + gid;
            int kr = j * 16 + 2 * tig;
            __half2 a = __halves2half2(kv[kr * HSTR + d],       kv[(kr + 1) * HSTR + d]);
            __half2 c = __halves2half2(kv[(kr + 8) * HSTR + d], kv[(kr + 9) * HSTR + d]);
            uint2 w;
            w.x = *(uint32_t*)&a;
            w.y = *(uint32_t*)&c;
            vo[q] = w;
        }
    }
}

// ---------------------------------------------------------------------------
// fp16 GEMM — exact round-14 configuration (the measured best):
// 2-stage bulk pipeline, 3 CTAs/SM, register-lean inner loop.
// SMEM: [A0 16K][A1 16K][B0 16K][B1 16K][mbar0 8][mbar1 8]
// ---------------------------------------------------------------------------
#define GEMM_SMEM_BYTES (65536 + 16)

__global__ __launch_bounds__(128, 3) void gemm_h(
    const __half* __restrict__ A, const __half* __restrict__ Bw,
    const float* __restrict__ bias, float* __restrict__ C,
    __half* __restrict__ Ch,
    int M, int N, int K, int out_half)
{
    extern __shared__ char smc[];
    const uint32_t sb = smem_u32(smc);
    const uint32_t mb = sb + 65536;
    const int tid  = threadIdx.x;
    const int wid  = tid >> 5;
    const int lane = tid & 31;
    const int gid  = lane >> 2;
    const int tig  = lane & 3;
    const int wm8  = (wid >> 1) * 4;
    const int wn16 = (wid & 1) * 8;
    const int m0 = blockIdx.y * 128;
    const int n0 = blockIdx.x * 128;
    const int KT = K / 64;

    if (tid == 0) {
        MBAR_INIT(mb, 1);
        MBAR_INIT(mb + 8, 1);
        FENCE_PROXY();
    }
    __syncthreads();

    float acc[4][8][4];
#pragma unroll
    for (int i = 0; i < 4; i++)
#pragma unroll
        for (int j = 0; j < 8; j++)
#pragma unroll
            for (int r = 0; r < 4; r++) acc[i][j][r] = 0.f;

    const __half* abase = A + ((size_t)blockIdx.y * KT) * 8192;
    const __half* bbase = Bw + ((size_t)blockIdx.x * KT) * 8192;

    auto load_stage = [&](int chunk, int stage) {
        MBAR_EXPECT_TX(mb + stage * 8, 32768);
        BULK_CP(sb + stage * 16384,         abase + (size_t)chunk * 8192, 16384, mb + stage * 8);
        BULK_CP(sb + 32768 + stage * 16384, bbase + (size_t)chunk * 8192, 16384, mb + stage * 8);
    };

    if (tid == 0) load_stage(0, 0);

    for (int j = 0; j < KT; j++) {
        MBAR_WAIT(mb + (j & 1) * 8, (j >> 1) & 1);
        __syncthreads();
        if (tid == 0 && j + 1 < KT) load_stage(j + 1, (j + 1) & 1);

        const int stage = j & 1;
        const uint4* at4 = (const uint4*)(smc + stage * 16384);
        const uint2* bt2 = (const uint2*)(smc + 32768 + stage * 16384);

#pragma unroll
        for (int ks = 0; ks < 4; ks++) {
            uint2 bfr[8];
#pragma unroll
            for (int nt = 0; nt < 8; nt++)
                bfr[nt] = bt2[(((wn16 + nt) * 4 + ks) << 5) + lane];
#pragma unroll
            for (int mt = 0; mt < 4; mt++) {
                uint4 afr = at4[(((wm8 + mt) * 4 + ks) << 5) + lane];
#pragma unroll
                for (int nt = 0; nt < 8; nt++)
                    mma_f16(acc[mt][nt],
                            (const uint32_t*)&afr,
                            (const uint32_t*)&bfr[nt]);
            }
        }
    }

#pragma unroll
    for (int mt = 0; mt < 4; mt++) {
        const int row = m0 + (wid >> 1) * 64 + mt * 16 + gid;
#pragma unroll
        for (int nt = 0; nt < 8; nt++) {
            const int col = n0 + (wid & 1) * 64 + nt * 8 + tig * 2;
            float2 bv = *(const float2*)(bias + col);
            float o0x = acc[mt][nt][0] + bv.x;
            float o0y = acc[mt][nt][1] + bv.y;
            float o1x = acc[mt][nt][2] + bv.x;
            float o1y = acc[mt][nt][3] + bv.y;
            if (out_half) {
                *(uint32_t*)(Ch + (size_t)row * N + col) = f2h2(o0x, o0y);
                *(uint32_t*)(Ch + (size_t)(row + 8) * N + col) = f2h2(o1x, o1y);
            } else {
                *(float2*)(C + (size_t)row * N + col) = make_float2(o0x, o0y);
                *(float2*)(C + (size_t)(row + 8) * N + col) = make_float2(o1x, o1y);
            }
        }
    }
}

// ---------------------------------------------------------------------------
// fp16 flash attention — ROUND 16: 3-stage KV bulk ring (two tiles always in
// flight -> per-iter mbar wait pre-satisfied). Costs 16KB smem, 0 regs.
// SMEM: [T0 16K][T1 16K][T2 16K][mbar x3]
// ---------------------------------------------------------------------------
#define ASTG 3
#define ATT_SMEM_BYTES (ASTG * 16384 + 24)   // 49176

__global__ __launch_bounds__(128, 2) void attn_h(
    const __half* __restrict__ qkvh, const __half* __restrict__ kvp,
    __half* __restrict__ valsp)
{
    extern __shared__ char smc[];
    const uint32_t sb = smem_u32(smc);
    const uint32_t mb = sb + ASTG * 16384;

    const int tid  = threadIdx.x;
    const int wid  = tid >> 5;
    const int lane = tid & 31;
    const int gid  = lane >> 2;
    const int tig  = lane & 3;
    const int b  = blockIdx.z;
    const int h  = blockIdx.y;
    const int q0 = blockIdx.x * 128;

    const float qs = 0.125f * 1.4426950408889634f;

    if (tid == 0) {
        MBAR_INIT(mb, 1);
        MBAR_INIT(mb + 8, 1);
        MBAR_INIT(mb + 16, 1);
        FENCE_PROXY();
    }
    __syncthreads();

    uint32_t qf[2][4][4];
#pragma unroll
    for (int m = 0; m < 2; m++) {
        const __half* qlo = qkvh + (size_t)(b * SS + q0 + wid * 32 + m * 16 + gid) * QKV_N + h * 192;
        const __half* qhi = qlo + 8 * QKV_N;
#pragma unroll
        for (int ks = 0; ks < 4; ks++) {
            const int kb = ks * 16 + 2 * tig;
            qf[m][ks][0] = f2h2(__half2float(qlo[kb]) * qs,     __half2float(qlo[kb + 1]) * qs);
            qf[m][ks][1] = f2h2(__half2float(qhi[kb]) * qs,     __half2float(qhi[kb + 1]) * qs);
            qf[m][ks][2] = f2h2(__half2float(qlo[kb + 8]) * qs, __half2float(qlo[kb + 9]) * qs);
            qf[m][ks][3] = f2h2(__half2float(qhi[kb + 8]) * qs, __half2float(qhi[kb + 9]) * qs);
        }
    }

    const __half* kvbase = kvp + (size_t)(b * HH + h) * 32 * 8192;
    auto load_tile = [&](int kt, int stage) {
        MBAR_EXPECT_TX(mb + stage * 8, 16384);
        BULK_CP(sb + stage * 16384, kvbase + (size_t)kt * 8192, 16384, mb + stage * 8);
    };

    float mx[2][2], lx[2][2];
#pragma unroll
    for (int m = 0; m < 2; m++) {
        mx[m][0] = mx[m][1] = -1e30f;
        lx[m][0] = lx[m][1] = 0.f;
    }
    float oacc[2][8][4];
#pragma unroll
    for (int m = 0; m < 2; m++)
#pragma unroll
        for (int nt = 0; nt < 8; nt++)
#pragma unroll
            for (int r = 0; r < 4; r++) oacc[m][nt][r] = 0.f;

    if (tid == 0) {
        load_tile(0, 0);
        load_tile(1, 1);
    }

    const int NT = SS / 64;
    int cstage = 0, phase = 0, pcount = 0;
    for (int kt = 0; kt < NT; kt++) {
        MBAR_WAIT(mb + cstage * 8, phase);
        __syncthreads();   // all warps done with tile kt-1 -> stage (kt+2)%3 free
        if (tid == 0 && kt + 2 < NT) {
            int ls = cstage == 0 ? 2 : cstage - 1;   // (kt+2)%3
            load_tile(kt + 2, ls);
        }

        const uint2* kp2 = (const uint2*)(smc + cstage * 16384);
        const uint2* vp2 = kp2 + 1024;

        // ---- S = Q @ K^T ----
        float sacc[2][8][4];
#pragma unroll
        for (int m = 0; m < 2; m++)
#pragma unroll
            for (int nt = 0; nt < 8; nt++)
#pragma unroll
                for (int r = 0; r < 4; r++) sacc[m][nt][r] = 0.f;

#pragma unroll
        for (int ks = 0; ks < 4; ks++) {
            uint2 kfr[8];
#pragma unroll
            for (int nt = 0; nt < 8; nt++)
                kfr[nt] = kp2[((nt * 4 + ks) << 5) + lane];
#pragma unroll
            for (int m = 0; m < 2; m++)
#pragma unroll
                for (int nt = 0; nt < 8; nt++)
                    mma_f16(sacc[m][nt], qf[m][ks], (const uint32_t*)&kfr[nt]);
        }

        // ---- online softmax (max reduced; l lane-local) ----
        uint32_t pf[2][4][4];
#pragma unroll
        for (int m = 0; m < 2; m++) {
            float tmax0 = -1e30f, tmax1 = -1e30f;
#pragma unroll
            for (int nt = 0; nt < 8; nt++) {
                tmax0 = fmaxf(tmax0, fmaxf(sacc[m][nt][0], sacc[m][nt][1]));
                tmax1 = fmaxf(tmax1, fmaxf(sacc[m][nt][2], sacc[m][nt][3]));
            }
            tmax0 = fmaxf(tmax0, __shfl_xor_sync(0xffffffffu, tmax0, 1));
            tmax0 = fmaxf(tmax0, __shfl_xor_sync(0xffffffffu, tmax0, 2));
            tmax1 = fmaxf(tmax1, __shfl_xor_sync(0xffffffffu, tmax1, 1));
            tmax1 = fmaxf(tmax1, __shfl_xor_sync(0xffffffffu, tmax1, 2));

            const float mn0 = fmaxf(mx[m][0], tmax0);
            const float mn1 = fmaxf(mx[m][1], tmax1);
            const float corr0 = ex2(mx[m][0] - mn0);
            const float corr1 = ex2(mx[m][1] - mn1);
            mx[m][0] = mn0;
            mx[m][1] = mn1;

            float sum0 = 0.f, sum1 = 0.f;
#pragma unroll
            for (int nt = 0; nt < 8; nt++) {
                float p0 = ex2(sacc[m][nt][0] - mn0);
                float p1 = ex2(sacc[m][nt][1] - mn0);
                float p2 = ex2(sacc[m][nt][2] - mn1);
                float p3 = ex2(sacc[m][nt][3] - mn1);
                sum0 += p0 + p1;
                sum1 += p2 + p3;
                const int j = nt >> 1;
                if ((nt & 1) == 0) {
                    pf[m][j][0] = f2h2(p0, p1);
                    pf[m][j][1] = f2h2(p2, p3);
                } else {
                    pf[m][j][2] = f2h2(p0, p1);
                    pf[m][j][3] = f2h2(p2, p3);
                }
            }
#pragma unroll
            for (int nt = 0; nt < 8; nt++) {
                oacc[m][nt][0] *= corr0;
                oacc[m][nt][1] *= corr0;
                oacc[m][nt][2] *= corr1;
                oacc[m][nt][3] *= corr1;
            }
            lx[m][0] = lx[m][0] * corr0 + sum0;
            lx[m][1] = lx[m][1] * corr1 + sum1;
        }

        // ---- O += P @ V ----
#pragma unroll
        for (int j = 0; j < 4; j++) {
            uint2 vfr[8];
#pragma unroll
            for (int nt = 0; nt < 8; nt++)
                vfr[nt] = vp2[((j * 8 + nt) << 5) + lane];
#pragma unroll
            for (int m = 0; m < 2; m++)
#pragma unroll
                for (int nt = 0; nt < 8; nt++)
                    mma_f16(oacc[m][nt], pf[m][j], (const uint32_t*)&vfr[nt]);
        }

        cstage = (cstage == ASTG - 1) ? 0 : cstage + 1;
        if (++pcount == ASTG) { pcount = 0; phase ^= 1; }
    }

    // ---- epilogue: quad-reduce l, normalize, write A-frag-packed fp16 ----
    {
        const size_t mtile = (size_t)(b * SS + q0) >> 7;
        uint4* o = (uint4*)(valsp + (mtile * 16 + h) * 8192);
#pragma unroll
        for (int m = 0; m < 2; m++) {
            float l0 = lx[m][0], l1 = lx[m][1];
            l0 += __shfl_xor_sync(0xffffffffu, l0, 1);
            l0 += __shfl_xor_sync(0xffffffffu, l0, 2);
            l1 += __shfl_xor_sync(0xffffffffu, l1, 1);
            l1 += __shfl_xor_sync(0xffffffffu, l1, 2);
            const float inv0 = 1.f / l0;
            const float inv1 = 1.f / l1;
            const int grp = wid * 2 + m;
#pragma unroll
            for (int ks = 0; ks < 4; ks++) {
                uint4 w;
                w.x = f2h2(oacc[m][2 * ks][0] * inv0,     oacc[m][2 * ks][1] * inv0);
                w.y = f2h2(oacc[m][2 * ks][2] * inv1,     oacc[m][2 * ks][3] * inv1);
                w.z = f2h2(oacc[m][2 * ks + 1][0] * inv0, oacc[m][2 * ks + 1][1] * inv0);
                w.w = f2h2(oacc[m][2 * ks + 1][2] * inv1, oacc[m][2 * ks + 1][3] * inv1);
                o[((grp * 4 + ks) << 5) + lane] = w;
            }
        }
    }
}

// ---------------------------------------------------------------------------
// Launch
// ---------------------------------------------------------------------------
extern "C" void kernel_launch(void* const* d_in, const int* in_sizes, int n_in,
                              void* d_out, int out_size)
{
    const float* x      = (const float*)d_in[0];
    const float* w_qkv  = (const float*)d_in[1];
    const float* b_qkv  = (const float*)d_in[2];
    const float* w_o    = (const float*)d_in[3];
    const float* b_o    = (const float*)d_in[4];
    float* out = (float*)d_out;

    __half *qkvh, *xc, *valsp, *wqc, *woc, *kvp;
    cudaGetSymbolAddress((void**)&qkvh,  g_qkvh);
    cudaGetSymbolAddress((void**)&xc,    g_xc);
    cudaGetSymbolAddress((void**)&valsp, g_valsp);
    cudaGetSymbolAddress((void**)&wqc,   g_wqc);
    cudaGetSymbolAddress((void**)&woc,   g_woc);
    cudaGetSymbolAddress((void**)&kvp,   g_kvp);

    cudaFuncSetAttribute(gemm_h,
                         cudaFuncAttributeMaxDynamicSharedMemorySize,
                         GEMM_SMEM_BYTES);
    cudaFuncSetAttribute(attn_h,
                         cudaFuncAttributeMaxDynamicSharedMemorySize,
                         ATT_SMEM_BYTES);

    // 0) fragment-pack GEMM inputs into fp16
    pack_a_h<<<(M_ROWS / 128) * (DIN / 64), 256>>>(x, xc, DIN);
    pack_b_h<<<(QKV_N / 128) * (DIN / 64), 256>>>(w_qkv, wqc, DIN);
    pack_b_h<<<(DD / 128) * (DIN / 64), 256>>>(w_o, woc, DIN);

    // 1) QKV projection -> g_qkvh (fp16 row-major)
    {
        dim3 grid(QKV_N / 128, M_ROWS / 128);
        gemm_h<<<grid, 128, GEMM_SMEM_BYTES>>>(
            xc, wqc, b_qkv, nullptr, qkvh, M_ROWS, QKV_N, DIN, 1);
    }

    // 1b) fragment-pack K/V tiles
    {
        dim3 grid(SS / 64, HH, BB);
        pack_kv_h<<<grid, 256>>>(qkvh, kvp);
    }

    // 2) Attention -> g_valsp (fp16 A-frag-packed)
    {
        dim3 grid(SS / 128, HH, BB);
        attn_h<<<grid, 128, ATT_SMEM_BYTES>>>(qkvh, kvp, valsp);
    }

    // 3) O-projection -> out (fp32)
    {
        dim3 grid(DD / 128, M_ROWS / 128);
        gemm_h<<<grid, 128, GEMM_SMEM_BYTES>>>(
            valsp, woc, b_o, out, nullptr, M_ROWS, DD, DIN, 0);
    }
}

// round 17
// speedup vs baseline: 1.0490x; 1.0366x over previous
#include <cuda_runtime.h>
#include <cuda_fp16.h>
#include <cstdint>
#include <math.h>

// Problem constants
#define BB   2
#define SS   2048
#define DIN  1024
#define DD   1024
#define HH   16
#define HDIM 64
#define M_ROWS (BB * SS)      // 4096
#define QKV_N  (3 * DD)       // 3072

// Scratch
__device__ __half g_qkvh [M_ROWS * QKV_N];
__device__ __half g_xc   [M_ROWS * DIN];
__device__ __half g_valsp[M_ROWS * DD];
__device__ __half g_wqc  [QKV_N * DIN];
__device__ __half g_woc  [DD * DD];
__device__ __half g_kvp  [BB * HH * 32 * 8192];

// ---------------------------------------------------------------------------
// Helpers
// ---------------------------------------------------------------------------
__device__ __forceinline__ uint32_t smem_u32(const void* p) {
    uint32_t a;
    asm("{ .reg .u64 t; cvta.to.shared.u64 t, %1; cvt.u32.u64 %0, t; }"
        : "=r"(a) : "l"(p));
    return a;
}

__device__ __forceinline__ uint32_t f2h2(float a, float b) {
    __half2 h = __floats2half2_rn(a, b);
    return *(uint32_t*)&h;
}

__device__ __forceinline__ float ex2(float x) {
    float r;
    asm("ex2.approx.f32 %0, %1;" : "=f"(r) : "f"(x));
    return r;
}

// fp16x2 exp2: one MUFU op yields two p values already packed.
__device__ __forceinline__ uint32_t h2ex2(uint32_t x) {
    uint32_t r;
    asm("ex2.approx.f16x2 %0, %1;" : "=r"(r) : "r"(x));
    return r;
}

__device__ __forceinline__ void mma_f16(float* d, const uint32_t* a, const uint32_t* b) {
    asm("mma.sync.aligned.m16n8k16.row.col.f32.f16.f16.f32 "
        "{%0,%1,%2,%3}, {%4,%5,%6,%7}, {%8,%9}, {%0,%1,%2,%3};"
        : "+f"(d[0]), "+f"(d[1]), "+f"(d[2]), "+f"(d[3])
        : "r"(a[0]), "r"(a[1]), "r"(a[2]), "r"(a[3]),
          "r"(b[0]), "r"(b[1]));
}

#define MBAR_INIT(mbar, cnt) \
    asm volatile("mbarrier.init.shared.b64 [%0], %1;" \
        :: "r"((uint32_t)(mbar)), "r"((uint32_t)(cnt)) : "memory")

#define MBAR_EXPECT_TX(mbar, bytes) \
    asm volatile("mbarrier.arrive.expect_tx.shared.b64 _, [%0], %1;" \
        :: "r"((uint32_t)(mbar)), "r"((uint32_t)(bytes)) : "memory")

#define MBAR_WAIT(mbar, parity) do { \
    asm volatile( \
        "{\n\t.reg .pred P1;\n\t" \
        "WL_%=:\n\t" \
        "mbarrier.try_wait.parity.shared.b64 P1, [%0], %1;\n\t" \
        "@P1 bra.uni WD_%=;\n\t" \
        "bra.uni WL_%=;\n\t" \
        "WD_%=:\n\t}" \
        :: "r"((uint32_t)(mbar)), "r"((uint32_t)(parity)) : "memory"); \
} while (0)

#define BULK_CP(dst, src, bytes, mbar) \
    asm volatile("cp.async.bulk.shared::cluster.global.mbarrier::complete_tx::bytes " \
        "[%0], [%1], %2, [%3];" \
        :: "r"((uint32_t)(dst)), "l"(src), "r"((uint32_t)(bytes)), \
           "r"((uint32_t)(mbar)) : "memory")

#define FENCE_PROXY() asm volatile("fence.proxy.async.shared::cta;" ::: "memory")

// ---------------------------------------------------------------------------
// Pack kernels (unchanged).
// ---------------------------------------------------------------------------
#define PSTR 68

__global__ __launch_bounds__(256) void pack_a_h(
    const float* __restrict__ src, __half* __restrict__ dst, int K)
{
    __shared__ float sm[128 * PSTR];
    const int tid = threadIdx.x;
    const int KT = K / 64;
    const int kt = blockIdx.x % KT;
    const int mt = blockIdx.x / KT;
    const float* g = src + (size_t)(mt * 128) * K + kt * 64;
#pragma unroll
    for (int it = 0; it < 8; it++) {
        int idx = it * 256 + tid;
        int r = idx >> 4;
        int c4 = (idx & 15) * 4;
        *(float4*)&sm[r * PSTR + c4] = *(const float4*)(g + (size_t)r * K + c4);
    }
    __syncthreads();
    uint4* o = (uint4*)(dst + (size_t)blockIdx.x * 8192);
#pragma unroll
    for (int it = 0; it < 4; it++) {
        int q = it * 256 + tid;
        int grp = q >> 7;
        int ks = (q >> 5) & 3;
        int lane = q & 31;
        int gid = lane >> 2, tig = lane & 3;
        int r0 = grp * 16 + gid;
        int kb = ks * 16 + 2 * tig;
        uint4 w;
        w.x = f2h2(sm[r0 * PSTR + kb],           sm[r0 * PSTR + kb + 1]);
        w.y = f2h2(sm[(r0 + 8) * PSTR + kb],     sm[(r0 + 8) * PSTR + kb + 1]);
        w.z = f2h2(sm[r0 * PSTR + kb + 8],       sm[r0 * PSTR + kb + 9]);
        w.w = f2h2(sm[(r0 + 8) * PSTR + kb + 8], sm[(r0 + 8) * PSTR + kb + 9]);
        o[q] = w;
    }
}

__global__ __launch_bounds__(256) void pack_b_h(
    const float* __restrict__ src, __half* __restrict__ dst, int K)
{
    __shared__ float sm[128 * PSTR];
    const int tid = threadIdx.x;
    const int KT = K / 64;
    const int kt = blockIdx.x % KT;
    const int nt = blockIdx.x / KT;
    const float* g = src + (size_t)(nt * 128) * K + kt * 64;
#pragma unroll
    for (int it = 0; it < 8; it++) {
        int idx = it * 256 + tid;
        int r = idx >> 4;
        int c4 = (idx & 15) * 4;
        *(float4*)&sm[r * PSTR + c4] = *(const float4*)(g + (size_t)r * K + c4);
    }
    __syncthreads();
    uint2* o = (uint2*)(dst + (size_t)blockIdx.x * 8192);
#pragma unroll
    for (int it = 0; it < 8; it++) {
        int q = it * 256 + tid;
        int ngrp = q >> 7;
        int ks = (q >> 5) & 3;
        int lane = q & 31;
        int gid = lane >> 2, tig = lane & 3;
        int n = ngrp * 8 + gid;
        int kb = ks * 16 + 2 * tig;
        uint2 w;
        w.x = f2h2(sm[n * PSTR + kb],     sm[n * PSTR + kb + 1]);
        w.y = f2h2(sm[n * PSTR + kb + 8], sm[n * PSTR + kb + 9]);
        o[q] = w;
    }
}

#define HSTR 136
__global__ __launch_bounds__(256) void pack_kv_h(
    const __half* __restrict__ qkvh, __half* __restrict__ kvp)
{
    __shared__ __half kv[64 * HSTR];
    const int tid = threadIdx.x;
    const int kt = blockIdx.x;
    const int h  = blockIdx.y;
    const int b  = blockIdx.z;

    const __half* src = qkvh + (size_t)(b * SS + kt * 64) * QKV_N + h * 192 + 64;
#pragma unroll
    for (int it = 0; it < 4; it++) {
        int idx = it * 256 + tid;
        int row = idx >> 4;
        int c8  = (idx & 15) * 8;
        *(uint4*)&kv[row * HSTR + c8] = *(const uint4*)(src + (size_t)row * QKV_N + c8);
    }
    __syncthreads();

    uint2* ko = (uint2*)(kvp + (size_t)((b * HH + h) * 32 + kt) * 8192);
    uint2* vo = ko + 1024;
#pragma unroll
    for (int it = 0; it < 4; it++) {
        int q = it * 256 + tid;
        int lane = q & 31;
        int gid = lane >> 2, tig = lane & 3;
        {
            int nt = q >> 7;
            int ks = (q >> 5) & 3;
            int key = nt * 8 + gid;
            int kb = ks * 16 + 2 * tig;
            uint2 w;
            w.x = *(const uint32_t*)&kv[key * HSTR + kb];
            w.y = *(const uint32_t*)&kv[key * HSTR + kb + 8];
            ko[q] = w;
        }
        {
            int j = q >> 8;
            int nt2 = (q >> 5) & 7;
            int d = 64 + nt2 * 8 + gid;
            int kr = j * 16 + 2 * tig;
            __half2 a = __halves2half2(kv[kr * HSTR + d],       kv[(kr + 1) * HSTR + d]);
            __half2 c = __halves2half2(kv[(kr + 8) * HSTR + d], kv[(kr + 9) * HSTR + d]);
            uint2 w;
            w.x = *(uint32_t*)&a;
            w.y = *(uint32_t*)&c;
            vo[q] = w;
        }
    }
}

// ---------------------------------------------------------------------------
// fp16 GEMM — round-14 configuration (measured best), unchanged.
// ---------------------------------------------------------------------------
#define GEMM_SMEM_BYTES (65536 + 16)

__global__ __launch_bounds__(128, 3) void gemm_h(
    const __half* __restrict__ A, const __half* __restrict__ Bw,
    const float* __restrict__ bias, float* __restrict__ C,
    __half* __restrict__ Ch,
    int M, int N, int K, int out_half)
{
    extern __shared__ char smc[];
    const uint32_t sb = smem_u32(smc);
    const uint32_t mb = sb + 65536;
    const int tid  = threadIdx.x;
    const int wid  = tid >> 5;
    const int lane = tid & 31;
    const int gid  = lane >> 2;
    const int tig  = lane & 3;
    const int wm8  = (wid >> 1) * 4;
    const int wn16 = (wid & 1) * 8;
    const int m0 = blockIdx.y * 128;
    const int n0 = blockIdx.x * 128;
    const int KT = K / 64;

    if (tid == 0) {
        MBAR_INIT(mb, 1);
        MBAR_INIT(mb + 8, 1);
        FENCE_PROXY();
    }
    __syncthreads();

    float acc[4][8][4];
#pragma unroll
    for (int i = 0; i < 4; i++)
#pragma unroll
        for (int j = 0; j < 8; j++)
#pragma unroll
            for (int r = 0; r < 4; r++) acc[i][j][r] = 0.f;

    const __half* abase = A + ((size_t)blockIdx.y * KT) * 8192;
    const __half* bbase = Bw + ((size_t)blockIdx.x * KT) * 8192;

    auto load_stage = [&](int chunk, int stage) {
        MBAR_EXPECT_TX(mb + stage * 8, 32768);
        BULK_CP(sb + stage * 16384,         abase + (size_t)chunk * 8192, 16384, mb + stage * 8);
        BULK_CP(sb + 32768 + stage * 16384, bbase + (size_t)chunk * 8192, 16384, mb + stage * 8);
    };

    if (tid == 0) load_stage(0, 0);

    for (int j = 0; j < KT; j++) {
        MBAR_WAIT(mb + (j & 1) * 8, (j >> 1) & 1);
        __syncthreads();
        if (tid == 0 && j + 1 < KT) load_stage(j + 1, (j + 1) & 1);

        const int stage = j & 1;
        const uint4* at4 = (const uint4*)(smc + stage * 16384);
        const uint2* bt2 = (const uint2*)(smc + 32768 + stage * 16384);

#pragma unroll
        for (int ks = 0; ks < 4; ks++) {
            uint2 bfr[8];
#pragma unroll
            for (int nt = 0; nt < 8; nt++)
                bfr[nt] = bt2[(((wn16 + nt) * 4 + ks) << 5) + lane];
#pragma unroll
            for (int mt = 0; mt < 4; mt++) {
                uint4 afr = at4[(((wm8 + mt) * 4 + ks) << 5) + lane];
#pragma unroll
                for (int nt = 0; nt < 8; nt++)
                    mma_f16(acc[mt][nt],
                            (const uint32_t*)&afr,
                            (const uint32_t*)&bfr[nt]);
            }
        }
    }

#pragma unroll
    for (int mt = 0; mt < 4; mt++) {
        const int row = m0 + (wid >> 1) * 64 + mt * 16 + gid;
#pragma unroll
        for (int nt = 0; nt < 8; nt++) {
            const int col = n0 + (wid & 1) * 64 + nt * 8 + tig * 2;
            float2 bv = *(const float2*)(bias + col);
            float o0x = acc[mt][nt][0] + bv.x;
            float o0y = acc[mt][nt][1] + bv.y;
            float o1x = acc[mt][nt][2] + bv.x;
            float o1y = acc[mt][nt][3] + bv.y;
            if (out_half) {
                *(uint32_t*)(Ch + (size_t)row * N + col) = f2h2(o0x, o0y);
                *(uint32_t*)(Ch + (size_t)(row + 8) * N + col) = f2h2(o1x, o1y);
            } else {
                *(float2*)(C + (size_t)row * N + col) = make_float2(o0x, o0y);
                *(float2*)(C + (size_t)(row + 8) * N + col) = make_float2(o1x, o1y);
            }
        }
    }
}

// ---------------------------------------------------------------------------
// fp16 flash attention — ROUND 17:
//  * ex2.approx.f16x2 (MUFU halved; p lands pre-packed in pf layout)
//  * l accumulated via P @ ones MMA (no scalar sum adds, no epilogue shuffle)
//  * 2-stage KV ring (measured best)
// ---------------------------------------------------------------------------
#define ATT_SMEM_BYTES (32768 + 16)

__global__ __launch_bounds__(128, 2) void attn_h(
    const __half* __restrict__ qkvh, const __half* __restrict__ kvp,
    __half* __restrict__ valsp)
{
    extern __shared__ char smc[];
    const uint32_t sb = smem_u32(smc);
    const uint32_t mb = sb + 32768;

    const int tid  = threadIdx.x;
    const int wid  = tid >> 5;
    const int lane = tid & 31;
    const int gid  = lane >> 2;
    const int tig  = lane & 3;
    const int b  = blockIdx.z;
    const int h  = blockIdx.y;
    const int q0 = blockIdx.x * 128;

    const float qs = 0.125f * 1.4426950408889634f;
    const uint32_t onesb[2] = { 0x3C003C00u, 0x3C003C00u };   // half2(1,1) x2

    if (tid == 0) {
        MBAR_INIT(mb, 1);
        MBAR_INIT(mb + 8, 1);
        FENCE_PROXY();
    }
    __syncthreads();

    uint32_t qf[2][4][4];
#pragma unroll
    for (int m = 0; m < 2; m++) {
        const __half* qlo = qkvh + (size_t)(b * SS + q0 + wid * 32 + m * 16 + gid) * QKV_N + h * 192;
        const __half* qhi = qlo + 8 * QKV_N;
#pragma unroll
        for (int ks = 0; ks < 4; ks++) {
            const int kb = ks * 16 + 2 * tig;
            qf[m][ks][0] = f2h2(__half2float(qlo[kb]) * qs,     __half2float(qlo[kb + 1]) * qs);
            qf[m][ks][1] = f2h2(__half2float(qhi[kb]) * qs,     __half2float(qhi[kb + 1]) * qs);
            qf[m][ks][2] = f2h2(__half2float(qlo[kb + 8]) * qs, __half2float(qlo[kb + 9]) * qs);
            qf[m][ks][3] = f2h2(__half2float(qhi[kb + 8]) * qs, __half2float(qhi[kb + 9]) * qs);
        }
    }

    const __half* kvbase = kvp + (size_t)(b * HH + h) * 32 * 8192;
    auto load_tile = [&](int kt) {
        const int stage = kt & 1;
        MBAR_EXPECT_TX(mb + stage * 8, 16384);
        BULK_CP(sb + stage * 16384, kvbase + (size_t)kt * 8192, 16384, mb + stage * 8);
    };

    float mx[2][2];
#pragma unroll
    for (int m = 0; m < 2; m++) { mx[m][0] = mx[m][1] = -1e30f; }
    float lacc[2][4];
#pragma unroll
    for (int m = 0; m < 2; m++)
#pragma unroll
        for (int r = 0; r < 4; r++) lacc[m][r] = 0.f;
    float oacc[2][8][4];
#pragma unroll
    for (int m = 0; m < 2; m++)
#pragma unroll
        for (int nt = 0; nt < 8; nt++)
#pragma unroll
            for (int r = 0; r < 4; r++) oacc[m][nt][r] = 0.f;

    if (tid == 0) load_tile(0);

    const int NT = SS / 64;
    for (int kt = 0; kt < NT; kt++) {
        MBAR_WAIT(mb + (kt & 1) * 8, (kt >> 1) & 1);
        __syncthreads();
        if (tid == 0 && kt + 1 < NT) load_tile(kt + 1);

        const uint2* kp2 = (const uint2*)(smc + (kt & 1) * 16384);
        const uint2* vp2 = kp2 + 1024;

        // ---- S = Q @ K^T ----
        float sacc[2][8][4];
#pragma unroll
        for (int m = 0; m < 2; m++)
#pragma unroll
            for (int nt = 0; nt < 8; nt++)
#pragma unroll
                for (int r = 0; r < 4; r++) sacc[m][nt][r] = 0.f;

#pragma unroll
        for (int ks = 0; ks < 4; ks++) {
            uint2 kfr[8];
#pragma unroll
            for (int nt = 0; nt < 8; nt++)
                kfr[nt] = kp2[((nt * 4 + ks) << 5) + lane];
#pragma unroll
            for (int m = 0; m < 2; m++)
#pragma unroll
                for (int nt = 0; nt < 8; nt++)
                    mma_f16(sacc[m][nt], qf[m][ks], (const uint32_t*)&kfr[nt]);
        }

        // ---- online softmax (fp16x2 exp2; l via MMA) ----
        uint32_t pf[2][4][4];
#pragma unroll
        for (int m = 0; m < 2; m++) {
            float tmax0 = -1e30f, tmax1 = -1e30f;
#pragma unroll
            for (int nt = 0; nt < 8; nt++) {
                tmax0 = fmaxf(tmax0, fmaxf(sacc[m][nt][0], sacc[m][nt][1]));
                tmax1 = fmaxf(tmax1, fmaxf(sacc[m][nt][2], sacc[m][nt][3]));
            }
            tmax0 = fmaxf(tmax0, __shfl_xor_sync(0xffffffffu, tmax0, 1));
            tmax0 = fmaxf(tmax0, __shfl_xor_sync(0xffffffffu, tmax0, 2));
            tmax1 = fmaxf(tmax1, __shfl_xor_sync(0xffffffffu, tmax1, 1));
            tmax1 = fmaxf(tmax1, __shfl_xor_sync(0xffffffffu, tmax1, 2));

            const float mn0 = fmaxf(mx[m][0], tmax0);
            const float mn1 = fmaxf(mx[m][1], tmax1);
            const float corr0 = ex2(mx[m][0] - mn0);
            const float corr1 = ex2(mx[m][1] - mn1);
            mx[m][0] = mn0;
            mx[m][1] = mn1;

#pragma unroll
            for (int nt = 0; nt < 8; nt++) {
                const float d0 = sacc[m][nt][0] - mn0;
                const float d1 = sacc[m][nt][1] - mn0;
                const float d2 = sacc[m][nt][2] - mn1;
                const float d3 = sacc[m][nt][3] - mn1;
                const int j = nt >> 1;
                if ((nt & 1) == 0) {
                    pf[m][j][0] = h2ex2(f2h2(d0, d1));
                    pf[m][j][1] = h2ex2(f2h2(d2, d3));
                } else {
                    pf[m][j][2] = h2ex2(f2h2(d0, d1));
                    pf[m][j][3] = h2ex2(f2h2(d2, d3));
                }
            }
            // rescale accumulators
            lacc[m][0] *= corr0;
            lacc[m][1] *= corr0;
            lacc[m][2] *= corr1;
            lacc[m][3] *= corr1;
#pragma unroll
            for (int nt = 0; nt < 8; nt++) {
                oacc[m][nt][0] *= corr0;
                oacc[m][nt][1] *= corr0;
                oacc[m][nt][2] *= corr1;
                oacc[m][nt][3] *= corr1;
            }
            // l += P @ ones  (row sums on the tensor pipe)
#pragma unroll
            for (int j = 0; j < 4; j++)
                mma_f16(lacc[m], pf[m][j], onesb);
        }

        // ---- O += P @ V ----
#pragma unroll
        for (int j = 0; j < 4; j++) {
            uint2 vfr[8];
#pragma unroll
            for (int nt = 0; nt < 8; nt++)
                vfr[nt] = vp2[((j * 8 + nt) << 5) + lane];
#pragma unroll
            for (int m = 0; m < 2; m++)
#pragma unroll
                for (int nt = 0; nt < 8; nt++)
                    mma_f16(oacc[m][nt], pf[m][j], (const uint32_t*)&vfr[nt]);
        }
    }

    // ---- epilogue: normalize (lacc already full row sums), write packed ----
    {
        const size_t mtile = (size_t)(b * SS + q0) >> 7;
        uint4* o = (uint4*)(valsp + (mtile * 16 + h) * 8192);
#pragma unroll
        for (int m = 0; m < 2; m++) {
            const float inv0 = 1.f / lacc[m][0];
            const float inv1 = 1.f / lacc[m][2];
            const int grp = wid * 2 + m;
#pragma unroll
            for (int ks = 0; ks < 4; ks++) {
                uint4 w;
                w.x = f2h2(oacc[m][2 * ks][0] * inv0,     oacc[m][2 * ks][1] * inv0);
                w.y = f2h2(oacc[m][2 * ks][2] * inv1,     oacc[m][2 * ks][3] * inv1);
                w.z = f2h2(oacc[m][2 * ks + 1][0] * inv0, oacc[m][2 * ks + 1][1] * inv0);
                w.w = f2h2(oacc[m][2 * ks + 1][2] * inv1, oacc[m][2 * ks + 1][3] * inv1);
                o[((grp * 4 + ks) << 5) + lane] = w;
            }
        }
    }
}

// ---------------------------------------------------------------------------
// Launch
// ---------------------------------------------------------------------------
extern "C" void kernel_launch(void* const* d_in, const int* in_sizes, int n_in,
                              void* d_out, int out_size)
{
    const float* x      = (const float*)d_in[0];
    const float* w_qkv  = (const float*)d_in[1];
    const float* b_qkv  = (const float*)d_in[2];
    const float* w_o    = (const float*)d_in[3];
    const float* b_o    = (const float*)d_in[4];
    float* out = (float*)d_out;

    __half *qkvh, *xc, *valsp, *wqc, *woc, *kvp;
    cudaGetSymbolAddress((void**)&qkvh,  g_qkvh);
    cudaGetSymbolAddress((void**)&xc,    g_xc);
    cudaGetSymbolAddress((void**)&valsp, g_valsp);
    cudaGetSymbolAddress((void**)&wqc,   g_wqc);
    cudaGetSymbolAddress((void**)&woc,   g_woc);
    cudaGetSymbolAddress((void**)&kvp,   g_kvp);

    cudaFuncSetAttribute(gemm_h,
                         cudaFuncAttributeMaxDynamicSharedMemorySize,
                         GEMM_SMEM_BYTES);
    cudaFuncSetAttribute(attn_h,
                         cudaFuncAttributeMaxDynamicSharedMemorySize,
                         ATT_SMEM_BYTES);

    // 0) fragment-pack GEMM inputs into fp16
    pack_a_h<<<(M_ROWS / 128) * (DIN / 64), 256>>>(x, xc, DIN);
    pack_b_h<<<(QKV_N / 128) * (DIN / 64), 256>>>(w_qkv, wqc, DIN);
    pack_b_h<<<(DD / 128) * (DIN / 64), 256>>>(w_o, woc, DIN);

    // 1) QKV projection -> g_qkvh (fp16 row-major)
    {
        dim3 grid(QKV_N / 128, M_ROWS / 128);
        gemm_h<<<grid, 128, GEMM_SMEM_BYTES>>>(
            xc, wqc, b_qkv, nullptr, qkvh, M_ROWS, QKV_N, DIN, 1);
    }

    // 1b) fragment-pack K/V tiles
    {
        dim3 grid(SS / 64, HH, BB);
        pack_kv_h<<<grid, 256>>>(qkvh, kvp);
    }

    // 2) Attention -> g_valsp (fp16 A-frag-packed)
    {
        dim3 grid(SS / 128, HH, BB);
        attn_h<<<grid, 128, ATT_SMEM_BYTES>>>(qkvh, kvp, valsp);
    }

    // 3) O-projection -> out (fp32)
    {
        dim3 grid(DD / 128, M_ROWS / 128);
        gemm_h<<<grid, 128, GEMM_SMEM_BYTES>>>(
            valsp, woc, b_o, out, nullptr, M_ROWS, DD, DIN, 0);
    }
}